// round 9
// baseline (speedup 1.0000x reference)
#include <cuda_runtime.h>
#include <math.h>

#define BB 32
#define VV 518
#define SS 2048
#define BV (BB*VV)            // 16576 rows
#define NTOK (BB*SS)          // 65536
#define NW 16                 // warps per block
#define TS 128                // s-positions per block
#define NCH (SS/TS)           // 16 s-chunks per batch
#define NBLK (BB*NCH)         // 512 blocks
#define ROWBYTES (SS*4)       // 8192

// Persistent scratch (allocations forbidden). g_sum_*, g_done zero between
// launches (reset by the finishing block of k2; statically zero first call).
__device__ double g_sum_nll  = 0.0;
__device__ double g_sum_mask = 0.0;
__device__ unsigned int g_done = 0;
__device__ float g_rowpart[BV * NCH];  // per (b,v): 16 s-chunk partials of sum_s exp
__device__ float g_colsum[NTOK];       // per (b,s): sum_v exp
__device__ int   g_t64;                // 1 if target buffer is int64

// ---------------------------------------------------------------------------
// k1: single exp per element, feeding BOTH reductions. ASCENDING address
// order (bid 0 -> low addresses): leaves the tail of X resident in L2 for
// k2's reversed traversal.
// Block (b, chunk): warp w owns v-rows [vlo,vhi), lane owns 4 s-cols (float4).
// Block 0 additionally detects target dtype (odd 32-bit words all zero over
// 64 entries <=> little-endian int64 with values < 518).
// ---------------------------------------------------------------------------
__global__ __launch_bounds__(NW*32, 2)
void k1(const float* __restrict__ X, const int* __restrict__ t32) {
    __shared__ float s_col[NW][TS];

    const int tid = threadIdx.x, w = tid >> 5, lane = tid & 31;
    const int b = blockIdx.x >> 4;
    const int chunk = blockIdx.x & 15;
    const int s0 = chunk * TS;
    // v-split: warps 0..5 get 33 rows, 6..15 get 32 (6*33+10*32 = 518)
    const int vlo = w * 32 + min(w, 6);
    const int vhi = vlo + ((w < 6) ? 33 : 32);

    if (blockIdx.x == 0) {
        __shared__ int nz;
        if (tid == 0) nz = 0;
        __syncthreads();
        if (tid < 64 && t32[tid * 2 + 1] != 0) atomicOr(&nz, 1);
        __syncthreads();
        if (tid == 0) g_t64 = nz ? 0 : 1;
    }

    float c0 = 0.f, c1 = 0.f, c2 = 0.f, c3 = 0.f;
    const char* p = (const char*)(X + (size_t)b * VV * SS + s0)
                  + (size_t)lane * 16 + (size_t)vlo * ROWBYTES;
    float* rp_out = &g_rowpart[((size_t)b * VV + vlo) * NCH + chunk];

#pragma unroll 2
    for (int v = vlo; v < vhi; v++, p += ROWBYTES, rp_out += NCH) {
        float4 x = *(const float4*)p;
        float e0 = __expf(x.x), e1 = __expf(x.y);
        float e2 = __expf(x.z), e3 = __expf(x.w);
        c0 += e0; c1 += e1; c2 += e2; c3 += e3;
        float rp = (e0 + e1) + (e2 + e3);
#pragma unroll
        for (int o = 16; o; o >>= 1) rp += __shfl_xor_sync(0xffffffffu, rp, o);
        if (lane == 0) *rp_out = rp;
    }

    s_col[w][lane*4 + 0] = c0;
    s_col[w][lane*4 + 1] = c1;
    s_col[w][lane*4 + 2] = c2;
    s_col[w][lane*4 + 3] = c3;
    __syncthreads();

    if (tid < TS) {
        float t = 0.f;
#pragma unroll
        for (int c = 0; c < NW; c++) t += s_col[c][tid];   // fixed order
        g_colsum[b * SS + s0 + tid] = t;
    }
}

// ---------------------------------------------------------------------------
// k2: exp-free argmax pass over X in REVERSE tile order (bid 0 -> highest
// addresses, which k1 just left in L2; LRU reverse-scan => ~92% L2 hits,
// and k2 in turn leaves the head of X in L2 for the next replay's k1).
// NLL = log(colsum) - x[target] (direct gather). Last block finalizes.
// ---------------------------------------------------------------------------
__global__ __launch_bounds__(NW*32, 2)
void k2(const float* __restrict__ X, const void* __restrict__ tptr,
        float* __restrict__ out) {
    __shared__ float nc[VV];
    __shared__ float s_best[NW][TS];
    __shared__ int   s_bv[NW][TS];
    __shared__ double s_red[8];

    const int tid = threadIdx.x, w = tid >> 5, lane = tid & 31;
    const int tile = NBLK - 1 - blockIdx.x;        // reversed traversal
    const int b = tile >> 4;
    const int s0 = (tile & 15) * TS;
    const int vlo = w * 32 + min(w, 6);
    const int vhi = vlo + ((w < 6) ? 33 : 32);

    // c[v]: sum 16 chunk partials (fixed pairwise order), negate log
    for (int v = tid; v < VV; v += NW*32) {
        const float4* q = (const float4*)&g_rowpart[((size_t)b * VV + v) * NCH];
        float4 a = q[0], bq = q[1], cq = q[2], d = q[3];
        float s01 = ((a.x + a.y) + (a.z + a.w)) + ((bq.x + bq.y) + (bq.z + bq.w));
        float s23 = ((cq.x + cq.y) + (cq.z + cq.w)) + ((d.x + d.y) + (d.z + d.w));
        nc[v] = -__logf(s01 + s23);
    }
    __syncthreads();

    float best0 = -INFINITY, best1 = -INFINITY, best2 = -INFINITY, best3 = -INFINITY;
    int bv0 = 0, bv1 = 0, bv2 = 0, bv3 = 0;

    const char* p = (const char*)(X + (size_t)b * VV * SS + s0)
                  + (size_t)lane * 16 + (size_t)vlo * ROWBYTES;
    int v = vlo;
    for (; v + 4 <= vhi; v += 4, p += 4*ROWBYTES) {
        float4 x0 = *(const float4*)(p);
        float4 x1 = *(const float4*)(p + ROWBYTES);
        float4 x2 = *(const float4*)(p + 2*ROWBYTES);
        float4 x3 = *(const float4*)(p + 3*ROWBYTES);
        float n0 = nc[v], n1 = nc[v+1], n2 = nc[v+2], n3 = nc[v+3];
#define SEL1(X4, NC, VI)                                             \
        {                                                            \
            float a_ = (X4).x + (NC), b_ = (X4).y + (NC);            \
            float c_ = (X4).z + (NC), d_ = (X4).w + (NC);            \
            if (a_ > best0) { best0 = a_; bv0 = (VI); }              \
            if (b_ > best1) { best1 = b_; bv1 = (VI); }              \
            if (c_ > best2) { best2 = c_; bv2 = (VI); }              \
            if (d_ > best3) { best3 = d_; bv3 = (VI); }              \
        }
        SEL1(x0, n0, v);
        SEL1(x1, n1, v+1);
        SEL1(x2, n2, v+2);
        SEL1(x3, n3, v+3);
    }
    for (; v < vhi; v++, p += ROWBYTES) {
        float4 x0 = *(const float4*)(p);
        float n0 = nc[v];
        SEL1(x0, n0, v);
    }
#undef SEL1

    {
        int j0 = lane * 4;
        s_best[w][j0]   = best0; s_bv[w][j0]   = bv0;
        s_best[w][j0+1] = best1; s_bv[w][j0+1] = bv1;
        s_best[w][j0+2] = best2; s_bv[w][j0+2] = bv2;
        s_best[w][j0+3] = best3; s_bv[w][j0+3] = bv3;
    }
    __syncthreads();

    double nll_d = 0.0, mask_d = 0.0;
    if (tid < TS) {
        const int j = tid;
        int tgt;
        {
            int idx = b * SS + s0 + j;
            if (g_t64) tgt = (int)((const long long*)tptr)[idx];
            else       tgt = ((const int*)tptr)[idx];
        }
        float txt = X[(size_t)b * VV * SS + (size_t)tgt * SS + s0 + j];

        float tbest = -INFINITY;
        int tbv = 0;
#pragma unroll
        for (int c = 0; c < NW; c++) {           // ascending = first-max ties
            if (s_best[c][j] > tbest) { tbest = s_best[c][j]; tbv = s_bv[c][j]; }
        }
        float nll = __logf(g_colsum[b * SS + s0 + j]) - txt;

        int pt = (tbv < 128) ? 0 : (tbv < 289) ? 1 : (tbv < 390) ? 2 : 3;
        int tt = (tgt < 128) ? 0 : (tgt < 289) ? 1 : (tgt < 390) ? 2 : 3;
        float mask;
        if (pt != tt) {
            mask = 1.0f;
        } else if (pt == 0) {
            mask = 0.5f;
        } else {
            float denom = (pt == 1) ? 160.f : (pt == 2) ? 100.f : 128.f;
            mask = 0.5f * fabsf((float)(tbv - tgt)) / denom;
        }
        nll_d  = (double)nll;
        mask_d = (double)mask;

#pragma unroll
        for (int o = 16; o; o >>= 1) {
            nll_d  += __shfl_xor_sync(0xffffffffu, nll_d, o);
            mask_d += __shfl_xor_sync(0xffffffffu, mask_d, o);
        }
        if (lane == 0) { s_red[w] = nll_d; s_red[4 + w] = mask_d; }
    }
    __syncthreads();
    if (tid == 0) {
        double n = s_red[0] + s_red[1] + s_red[2] + s_red[3];
        double m = s_red[4] + s_red[5] + s_red[6] + s_red[7];
        atomicAdd(&g_sum_nll, n);
        atomicAdd(&g_sum_mask, m);
        __threadfence();
        unsigned int done = atomicAdd(&g_done, 1u);
        if (done == NBLK - 1) {
            double nm = g_sum_nll / (double)NTOK;
            double mm = g_sum_mask / (double)NTOK;
            out[0] = (float)(nm * (1.0 + mm));
            g_sum_nll = 0.0;
            g_sum_mask = 0.0;
            g_done = 0u;
        }
    }
}

extern "C" void kernel_launch(void* const* d_in, const int* in_sizes, int n_in,
                              void* d_out, int out_size) {
    const float* X   = (const float*)d_in[0];
    const void*  tgt = d_in[1];
    float* out = (float*)d_out;

    k1<<<NBLK, NW*32>>>(X, (const int*)tgt);
    k2<<<NBLK, NW*32>>>(X, tgt, out);
}